// round 6
// baseline (speedup 1.0000x reference)
#include <cuda_runtime.h>
#include <math.h>

// Problem constants
#define T_STEPS 16384
#define HDIM    1024
#define XDIM    256

// Recurrent kernel config
#define NCTA          128   // persistent CTAs (co-resident in wave 1)
#define ROWS_PER_CTA  8     // HDIM / NCTA
#define RNN_THREADS   256   // 8 warps, one row per warp
#define WATCHDOG_POLLS 4000000  // ~0.6 s of tight polling before abort

// Scratch (device globals: allocation-free per harness rules)
__device__ float g_bx[(size_t)T_STEPS * HDIM];   // Bx_c precompute, 64 MB
__device__ int   g_cnt[T_STEPS];                 // arrival counters (atomics only, never polled)
__device__ int   g_go[T_STEPS];                  // broadcast flags (polled, single writer)
__device__ int   g_abort;

// ---------------------------------------------------------------------------
// helpers
// ---------------------------------------------------------------------------
__device__ __forceinline__ int atom_acqrel_add(int* p, int v) {
    int old;
    asm volatile("atom.acq_rel.gpu.global.add.s32 %0, [%1], %2;"
                 : "=r"(old) : "l"(p), "r"(v) : "memory");
    return old;
}

__device__ __forceinline__ void st_release_gpu(int* p, int v) {
    asm volatile("st.release.gpu.global.s32 [%0], %1;" :: "l"(p), "r"(v) : "memory");
}

__device__ __forceinline__ int ldcg_i32(const int* p) {
    int v;
    asm volatile("ld.global.cg.s32 %0, [%1];" : "=r"(v) : "l"(p) : "memory");
    return v;
}

__device__ __forceinline__ void stg_i32(int* p, int v) {
    asm volatile("st.global.s32 [%0], %1;" :: "l"(p), "r"(v) : "memory");
}

__device__ __forceinline__ void fence_acq() {
    asm volatile("fence.acq_rel.gpu;" ::: "memory");
}

__device__ __forceinline__ float warp_sum(float v) {
#pragma unroll
    for (int s = 16; s > 0; s >>= 1)
        v += __shfl_xor_sync(0xffffffffu, v, s);
    return v;
}

// ---------------------------------------------------------------------------
// 0) zero counters + go flags + abort (graph replays reuse device globals)
// ---------------------------------------------------------------------------
__global__ void init_cnt_kernel() {
    int i = blockIdx.x * blockDim.x + threadIdx.x;
    g_cnt[i] = 0;
    g_go[i]  = 0;
    if (i == 0) g_abort = 0;
}

// ---------------------------------------------------------------------------
// 1) Bx_c = x_seq @ B^T + c   (T x H), fp32 tiled GEMM
// ---------------------------------------------------------------------------
__global__ __launch_bounds__(256) void gemm_bx_kernel(
    const float* __restrict__ x,   // (T, 256)
    const float* __restrict__ B,   // (1024, 256)
    const float* __restrict__ c)   // (1024,)
{
    __shared__ float xsT[32][132];
    __shared__ float bsT[32][68];

    const int bj  = blockIdx.x * 64;
    const int bt  = blockIdx.y * 128;
    const int tid = threadIdx.x;
    const int tx  = tid & 15;
    const int ty  = tid >> 4;

    float acc[8][4];
#pragma unroll
    for (int i = 0; i < 8; i++)
#pragma unroll
        for (int j = 0; j < 4; j++) acc[i][j] = 0.0f;

    for (int k0 = 0; k0 < XDIM; k0 += 32) {
#pragma unroll
        for (int i = 0; i < 4; i++) {
            int idx = tid + i * 256;
            int r   = idx >> 3;
            int kk4 = (idx & 7) * 4;
            float4 v = *(const float4*)&x[(size_t)(bt + r) * XDIM + k0 + kk4];
            xsT[kk4 + 0][r] = v.x; xsT[kk4 + 1][r] = v.y;
            xsT[kk4 + 2][r] = v.z; xsT[kk4 + 3][r] = v.w;
        }
#pragma unroll
        for (int i = 0; i < 2; i++) {
            int idx = tid + i * 256;
            int r   = idx >> 3;
            int kk4 = (idx & 7) * 4;
            float4 v = *(const float4*)&B[(size_t)(bj + r) * XDIM + k0 + kk4];
            bsT[kk4 + 0][r] = v.x; bsT[kk4 + 1][r] = v.y;
            bsT[kk4 + 2][r] = v.z; bsT[kk4 + 3][r] = v.w;
        }
        __syncthreads();

#pragma unroll
        for (int kk = 0; kk < 32; kk++) {
            float xr[8], br[4];
#pragma unroll
            for (int i = 0; i < 8; i++) xr[i] = xsT[kk][ty * 8 + i];
#pragma unroll
            for (int j = 0; j < 4; j++) br[j] = bsT[kk][tx * 4 + j];
#pragma unroll
            for (int i = 0; i < 8; i++)
#pragma unroll
                for (int j = 0; j < 4; j++)
                    acc[i][j] = fmaf(xr[i], br[j], acc[i][j]);
        }
        __syncthreads();
    }

#pragma unroll
    for (int i = 0; i < 8; i++) {
        int t = bt + ty * 8 + i;
#pragma unroll
        for (int j = 0; j < 4; j++) {
            int col = bj + tx * 4 + j;
            g_bx[(size_t)t * HDIM + col] = acc[i][j] + c[col];
        }
    }
}

// ---------------------------------------------------------------------------
// 2) persistent recurrent kernel: sense-reversing barrier.
//    Producers: atom.acq_rel.add(cnt[t]); last arriver st.release(go[t]=1).
//    Consumers: tight-poll go[t-1] (read-only line; no RMW starvation),
//    one fence after detect. Watchdog + fallback retained.
// ---------------------------------------------------------------------------
__global__ __launch_bounds__(RNN_THREADS, 1) void rnn_scan_kernel(
    const float* __restrict__ A_raw,  // (1024, 1024)
    const float* __restrict__ h0,     // (1024,)
    float* __restrict__ out)          // (16384, 1024)
{
    __shared__ int s_abort;
    const int b   = blockIdx.x;
    const int w   = threadIdx.x >> 5;
    const int l   = threadIdx.x & 31;
    const int row = b * ROWS_PER_CTA + w;

    if (threadIdx.x == 0) s_abort = 0;

    // Load A row segment into registers, applying A = 0.9*I + 0.1*A_raw
    float4 a[8];
#pragma unroll
    for (int i = 0; i < 8; i++) {
        int col  = 32 * l + 4 * i;
        float4 v = *(const float4*)&A_raw[(size_t)row * HDIM + col];
        v.x *= 0.1f; v.y *= 0.1f; v.z *= 0.1f; v.w *= 0.1f;
        int d = row - col;
        if (d == 0) v.x += 0.9f;
        else if (d == 1) v.y += 0.9f;
        else if (d == 2) v.z += 0.9f;
        else if (d == 3) v.w += 0.9f;
        a[i] = v;
    }
    __syncthreads();

    const float* hprev = h0;
    int won_prev = 0;   // thread0: did this CTA close the previous step?

    for (int t = 0; t < T_STEPS; t++) {
        // bias prefetch (independent of h -> overlaps wait)
        float bxv = 0.0f;
        if (l == 0) bxv = g_bx[(size_t)t * HDIM + row];

        if (t > 0) {
            if (threadIdx.x == 0) {
                if (!won_prev) {
                    const int* gp = &g_go[t - 1];
                    int polls = 0;
                    for (;;) {
                        if (ldcg_i32(gp)) break;           // tight poll, read-only line
                        if ((++polls & 4095) == 0) {       // rare slow path
                            if (ldcg_i32(&g_abort) || polls > WATCHDOG_POLLS) {
                                stg_i32(&g_abort, 1);
                                s_abort = 1;
                                break;
                            }
                        }
                    }
                    fence_acq();   // acquire ordering once, after detect
                }
                won_prev = 0;
            }
            __syncthreads();
            if (s_abort) return;   // uniform exit: fallback recomputes
            hprev = out + (size_t)(t - 1) * HDIM;
        }

        // dot product: 32 contiguous elements per lane
        const float4* h4 = (const float4*)(hprev + 32 * l);
        float a0 = 0.f, a1 = 0.f, a2 = 0.f, a3 = 0.f;
#pragma unroll
        for (int i = 0; i < 8; i++) {
            float4 hv = h4[i];
            a0 = fmaf(a[i].x, hv.x, a0);
            a1 = fmaf(a[i].y, hv.y, a1);
            a2 = fmaf(a[i].z, hv.z, a2);
            a3 = fmaf(a[i].w, hv.w, a3);
        }
        float acc = warp_sum((a0 + a1) + (a2 + a3));

        if (l == 0) {
            out[(size_t)t * HDIM + row] = tanhf(acc + bxv);
        }

        __syncthreads();  // all 8 rows stored before arrival
        if (threadIdx.x == 0) {
            int old = atom_acqrel_add(&g_cnt[t], 1);  // never-polled line
            if (old == NCTA - 1) {                    // last arriver broadcasts
                st_release_gpu(&g_go[t], 1);
                won_prev = 1;                          // skip own poll next step
            }
        }
    }
}

// ---------------------------------------------------------------------------
// 3) fallback: single-CTA full recompute; runs only if g_abort was set.
// ---------------------------------------------------------------------------
__global__ __launch_bounds__(1024) void fallback_scan_kernel(
    const float* __restrict__ A_raw,
    const float* __restrict__ h0,
    float* __restrict__ out)
{
    if (g_abort == 0) return;

    __shared__ float h[HDIM];
    __shared__ float hn[HDIM];
    const int tid = threadIdx.x;
    const int w   = tid >> 5;
    const int l   = tid & 31;

    h[tid] = h0[tid];
    __syncthreads();

    for (int t = 0; t < T_STEPS; t++) {
        for (int r = w; r < HDIM; r += 32) {
            const float* Ar = A_raw + (size_t)r * HDIM;
            float acc = 0.0f;
#pragma unroll 8
            for (int k = l; k < HDIM; k += 32)
                acc = fmaf(Ar[k], h[k], acc);
#pragma unroll
            for (int s = 16; s > 0; s >>= 1)
                acc += __shfl_xor_sync(0xffffffffu, acc, s);
            if (l == 0) {
                float v = tanhf(0.1f * acc + 0.9f * h[r] +
                                g_bx[(size_t)t * HDIM + r]);
                hn[r] = v;
                out[(size_t)t * HDIM + r] = v;
            }
        }
        __syncthreads();
        h[tid] = hn[tid];
        __syncthreads();
    }
}

// ---------------------------------------------------------------------------
// launch
// ---------------------------------------------------------------------------
extern "C" void kernel_launch(void* const* d_in, const int* in_sizes, int n_in,
                              void* d_out, int out_size) {
    const float* x_seq = (const float*)d_in[0];  // (16384, 256)
    const float* h0    = (const float*)d_in[1];  // (1024,)
    const float* A_raw = (const float*)d_in[2];  // (1024, 1024)
    const float* B     = (const float*)d_in[3];  // (1024, 256)
    const float* c     = (const float*)d_in[4];  // (1024,)
    float* out = (float*)d_out;                  // (16384, 1024)

    init_cnt_kernel<<<16, 1024>>>();
    gemm_bx_kernel<<<dim3(HDIM / 64, T_STEPS / 128), 256>>>(x_seq, B, c);
    rnn_scan_kernel<<<NCTA, RNN_THREADS>>>(A_raw, h0, out);
    fallback_scan_kernel<<<1, 1024>>>(A_raw, h0, out);
}

// round 7
// speedup vs baseline: 23.4803x; 23.4803x over previous
#include <cuda_runtime.h>
#include <math.h>

// Problem constants
#define T_STEPS 16384
#define HDIM    1024
#define XDIM    256

// Recurrent kernel config
#define NCTA          128   // persistent CTAs (co-resident in wave 1)
#define ROWS_PER_CTA  8     // HDIM / NCTA
#define RNN_THREADS   256   // 8 warps, one row per warp
#define WATCHDOG_POLLS 1000000  // ~0.2 s of atomic polling before abort

// Scratch (device globals: allocation-free per harness rules)
__device__ float g_bx[(size_t)T_STEPS * HDIM];   // Bx_c precompute, 64 MB
__device__ int   g_cnt[T_STEPS];                 // per-step arrival counters (RMW-only)
__device__ int   g_abort;

// ---------------------------------------------------------------------------
// helpers
// ---------------------------------------------------------------------------
__device__ __forceinline__ int atom_acqrel_add(int* p, int v) {
    int old;
    asm volatile("atom.acq_rel.gpu.global.add.s32 %0, [%1], %2;"
                 : "=r"(old) : "l"(p), "r"(v) : "memory");
    return old;
}

__device__ __forceinline__ int ldcg_i32(const int* p) {
    int v;
    asm volatile("ld.global.cg.s32 %0, [%1];" : "=r"(v) : "l"(p) : "memory");
    return v;
}

__device__ __forceinline__ void stg_i32(int* p, int v) {
    asm volatile("st.global.s32 [%0], %1;" :: "l"(p), "r"(v) : "memory");
}

__device__ __forceinline__ float warp_sum(float v) {
#pragma unroll
    for (int s = 16; s > 0; s >>= 1)
        v += __shfl_xor_sync(0xffffffffu, v, s);
    return v;
}

// ---------------------------------------------------------------------------
// 0) zero counters + abort (graph replays reuse device globals -> re-init)
// ---------------------------------------------------------------------------
__global__ void init_cnt_kernel() {
    int i = blockIdx.x * blockDim.x + threadIdx.x;
    g_cnt[i] = 0;
    if (i == 0) g_abort = 0;
}

// ---------------------------------------------------------------------------
// 1) Bx_c = x_seq @ B^T + c   (T x H), fp32 tiled GEMM
// ---------------------------------------------------------------------------
__global__ __launch_bounds__(256) void gemm_bx_kernel(
    const float* __restrict__ x,   // (T, 256)
    const float* __restrict__ B,   // (1024, 256)
    const float* __restrict__ c)   // (1024,)
{
    __shared__ float xsT[32][132];
    __shared__ float bsT[32][68];

    const int bj  = blockIdx.x * 64;
    const int bt  = blockIdx.y * 128;
    const int tid = threadIdx.x;
    const int tx  = tid & 15;
    const int ty  = tid >> 4;

    float acc[8][4];
#pragma unroll
    for (int i = 0; i < 8; i++)
#pragma unroll
        for (int j = 0; j < 4; j++) acc[i][j] = 0.0f;

    for (int k0 = 0; k0 < XDIM; k0 += 32) {
#pragma unroll
        for (int i = 0; i < 4; i++) {
            int idx = tid + i * 256;
            int r   = idx >> 3;
            int kk4 = (idx & 7) * 4;
            float4 v = *(const float4*)&x[(size_t)(bt + r) * XDIM + k0 + kk4];
            xsT[kk4 + 0][r] = v.x; xsT[kk4 + 1][r] = v.y;
            xsT[kk4 + 2][r] = v.z; xsT[kk4 + 3][r] = v.w;
        }
#pragma unroll
        for (int i = 0; i < 2; i++) {
            int idx = tid + i * 256;
            int r   = idx >> 3;
            int kk4 = (idx & 7) * 4;
            float4 v = *(const float4*)&B[(size_t)(bj + r) * XDIM + k0 + kk4];
            bsT[kk4 + 0][r] = v.x; bsT[kk4 + 1][r] = v.y;
            bsT[kk4 + 2][r] = v.z; bsT[kk4 + 3][r] = v.w;
        }
        __syncthreads();

#pragma unroll
        for (int kk = 0; kk < 32; kk++) {
            float xr[8], br[4];
#pragma unroll
            for (int i = 0; i < 8; i++) xr[i] = xsT[kk][ty * 8 + i];
#pragma unroll
            for (int j = 0; j < 4; j++) br[j] = bsT[kk][tx * 4 + j];
#pragma unroll
            for (int i = 0; i < 8; i++)
#pragma unroll
                for (int j = 0; j < 4; j++)
                    acc[i][j] = fmaf(xr[i], br[j], acc[i][j]);
        }
        __syncthreads();
    }

#pragma unroll
    for (int i = 0; i < 8; i++) {
        int t = bt + ty * 8 + i;
#pragma unroll
        for (int j = 0; j < 4; j++) {
            int col = bj + tx * 4 + j;
            g_bx[(size_t)t * HDIM + col] = acc[i][j] + c[col];
        }
    }
}

// ---------------------------------------------------------------------------
// 2) persistent recurrent kernel: ATOMIC-POLL barrier.
//    Producers: atom.acq_rel.add(cnt[t], 1).
//    Consumers: poll with atom.acq_rel.add(cnt[t-1], 0) -- read-via-RMW
//    enters the same L2 atomic FIFO as the increments, so the increments
//    can never be starved by the polling (the failure mode of R1/R5/R6).
// ---------------------------------------------------------------------------
__global__ __launch_bounds__(RNN_THREADS, 1) void rnn_scan_kernel(
    const float* __restrict__ A_raw,  // (1024, 1024)
    const float* __restrict__ h0,     // (1024,)
    float* __restrict__ out)          // (16384, 1024)
{
    __shared__ int s_abort;
    const int b   = blockIdx.x;
    const int w   = threadIdx.x >> 5;
    const int l   = threadIdx.x & 31;
    const int row = b * ROWS_PER_CTA + w;

    if (threadIdx.x == 0) s_abort = 0;

    // Load A row segment into registers, applying A = 0.9*I + 0.1*A_raw
    float4 a[8];
#pragma unroll
    for (int i = 0; i < 8; i++) {
        int col  = 32 * l + 4 * i;
        float4 v = *(const float4*)&A_raw[(size_t)row * HDIM + col];
        v.x *= 0.1f; v.y *= 0.1f; v.z *= 0.1f; v.w *= 0.1f;
        int d = row - col;
        if (d == 0) v.x += 0.9f;
        else if (d == 1) v.y += 0.9f;
        else if (d == 2) v.z += 0.9f;
        else if (d == 3) v.w += 0.9f;
        a[i] = v;
    }
    __syncthreads();

    const float* hprev = h0;
    int won_prev = 0;   // thread0: was this CTA the last arriver of prev step?

    for (int t = 0; t < T_STEPS; t++) {
        // bias prefetch (independent of h -> overlaps wait)
        float bxv = 0.0f;
        if (l == 0) bxv = g_bx[(size_t)t * HDIM + row];

        if (t > 0) {
            if (threadIdx.x == 0) {
                if (!won_prev) {
                    int* cp = &g_cnt[t - 1];
                    int polls = 0;
                    for (;;) {
                        if (atom_acqrel_add(cp, 0) >= NCTA) break;  // FIFO-fair poll
                        if ((++polls & 1023) == 0) {                // rare slow path
                            if (ldcg_i32(&g_abort) || polls > WATCHDOG_POLLS) {
                                stg_i32(&g_abort, 1);
                                s_abort = 1;
                                break;
                            }
                        }
                    }
                }
                won_prev = 0;
            }
            __syncthreads();
            if (s_abort) return;   // uniform exit: fallback recomputes
            hprev = out + (size_t)(t - 1) * HDIM;
        }

        // dot product: 32 contiguous elements per lane
        const float4* h4 = (const float4*)(hprev + 32 * l);
        float a0 = 0.f, a1 = 0.f, a2 = 0.f, a3 = 0.f;
#pragma unroll
        for (int i = 0; i < 8; i++) {
            float4 hv = h4[i];
            a0 = fmaf(a[i].x, hv.x, a0);
            a1 = fmaf(a[i].y, hv.y, a1);
            a2 = fmaf(a[i].z, hv.z, a2);
            a3 = fmaf(a[i].w, hv.w, a3);
        }
        float acc = warp_sum((a0 + a1) + (a2 + a3));

        if (l == 0) {
            out[(size_t)t * HDIM + row] = tanhf(acc + bxv);
        }

        __syncthreads();  // all 8 rows stored before arrival
        if (threadIdx.x == 0) {
            int old = atom_acqrel_add(&g_cnt[t], 1);   // publish arrival
            won_prev = (old == NCTA - 1);              // last arriver skips next poll
        }
    }
}

// ---------------------------------------------------------------------------
// 3) fallback: single-CTA full recompute; runs only if g_abort was set.
// ---------------------------------------------------------------------------
__global__ __launch_bounds__(1024) void fallback_scan_kernel(
    const float* __restrict__ A_raw,
    const float* __restrict__ h0,
    float* __restrict__ out)
{
    if (g_abort == 0) return;

    __shared__ float h[HDIM];
    __shared__ float hn[HDIM];
    const int tid = threadIdx.x;
    const int w   = tid >> 5;
    const int l   = tid & 31;

    h[tid] = h0[tid];
    __syncthreads();

    for (int t = 0; t < T_STEPS; t++) {
        for (int r = w; r < HDIM; r += 32) {
            const float* Ar = A_raw + (size_t)r * HDIM;
            float acc = 0.0f;
#pragma unroll 8
            for (int k = l; k < HDIM; k += 32)
                acc = fmaf(Ar[k], h[k], acc);
#pragma unroll
            for (int s = 16; s > 0; s >>= 1)
                acc += __shfl_xor_sync(0xffffffffu, acc, s);
            if (l == 0) {
                float v = tanhf(0.1f * acc + 0.9f * h[r] +
                                g_bx[(size_t)t * HDIM + r]);
                hn[r] = v;
                out[(size_t)t * HDIM + r] = v;
            }
        }
        __syncthreads();
        h[tid] = hn[tid];
        __syncthreads();
    }
}

// ---------------------------------------------------------------------------
// launch
// ---------------------------------------------------------------------------
extern "C" void kernel_launch(void* const* d_in, const int* in_sizes, int n_in,
                              void* d_out, int out_size) {
    const float* x_seq = (const float*)d_in[0];  // (16384, 256)
    const float* h0    = (const float*)d_in[1];  // (1024,)
    const float* A_raw = (const float*)d_in[2];  // (1024, 1024)
    const float* B     = (const float*)d_in[3];  // (1024, 256)
    const float* c     = (const float*)d_in[4];  // (1024,)
    float* out = (float*)d_out;                  // (16384, 1024)

    init_cnt_kernel<<<16, 1024>>>();
    gemm_bx_kernel<<<dim3(HDIM / 64, T_STEPS / 128), 256>>>(x_seq, B, c);
    rnn_scan_kernel<<<NCTA, RNN_THREADS>>>(A_raw, h0, out);
    fallback_scan_kernel<<<1, 1024>>>(A_raw, h0, out);
}